// round 7
// baseline (speedup 1.0000x reference)
#include <cuda_runtime.h>
#include <cuda_bf16.h>
#include <math.h>
#include <stdint.h>

#define NN 50000
#define EE 800000
#define BB 512
#define DD 128
#define KK 256
#define TM 128
#define GEMM_BLOCKS ((NN + TM - 1) / TM)   // 391

// ---------------- scratch (static device globals; no allocation) ----------------
__device__ float g_h1[NN * DD];
__device__ float g_h2[NN * DD];
// frag-packed bf16 operand storage: per row, 128 uint32 (= 256 bf16 as 128 col-pairs,
// permuted within each 16-col k-group so mma fragment halves are contiguous 8B)
__device__ uint32_t g_Ahi[NN * 128];
__device__ uint32_t g_Alo[NN * 128];
__device__ uint32_t g_Whi[3][DD * 128];
__device__ uint32_t g_Wlo[3][DD * 128];
__device__ float g_pool[BB * DD];
__device__ float g_invdeg[NN];
__device__ int   g_deg[NN];
__device__ int   g_rowptr[NN + 1];
__device__ int   g_col[EE];
__device__ int   g_root[BB];

__device__ __forceinline__ float* hbuf(int i) { return i == 2 ? g_h2 : g_h1; }

// packed uint32 index (within a 128-uint32 row) for column-pair index `pair` (0..127)
__device__ __forceinline__ int pk_idx(int pair) {
    int g = pair >> 3, pg = pair & 7;
    return g * 8 + ((pg & 3) << 1) + (pg >> 2);
}

// ---------------- fp32 -> bf16 hi/lo split ----------------
__device__ __forceinline__ void split2(float a, float b, uint32_t& hi, uint32_t& lo) {
    __nv_bfloat16 ha = __float2bfloat16(a);
    __nv_bfloat16 hb = __float2bfloat16(b);
    __nv_bfloat16 la = __float2bfloat16(a - __bfloat162float(ha));
    __nv_bfloat16 lb = __float2bfloat16(b - __bfloat162float(hb));
    hi = ((uint32_t)__bfloat16_as_ushort(hb) << 16) | __bfloat16_as_ushort(ha);
    lo = ((uint32_t)__bfloat16_as_ushort(lb) << 16) | __bfloat16_as_ushort(la);
}

// ---------------- init: zero deg + pool ----------------
__global__ void k_init() {
    int i = blockIdx.x * blockDim.x + threadIdx.x;
    if (i < NN) g_deg[i] = 0;
    if (i < BB * DD) ((int*)g_pool)[i] = 0;          // 0 bits == +0.0f
}

__global__ void k_count(const int* __restrict__ dst) {
    int e = blockIdx.x * blockDim.x + threadIdx.x;
    if (e < EE) atomicAdd(&g_deg[dst[e]], 1);
}

// exclusive scan + invdeg + cursor reset + roots, single block
__global__ void k_scan_fused(const int* __restrict__ batch) {
    __shared__ int wsum[32];
    __shared__ int carry;
    int tid = threadIdx.x;
    int warp = tid >> 5, lane = tid & 31;
    if (tid == 0) carry = 0;
    __syncthreads();
    for (int base = 0; base < NN; base += 1024) {
        int i = base + tid;
        int v = (i < NN) ? g_deg[i] : 0;
        int s = v;
#pragma unroll
        for (int off = 1; off < 32; off <<= 1) {
            int t = __shfl_up_sync(0xFFFFFFFFu, s, off);
            if (lane >= off) s += t;
        }
        if (lane == 31) wsum[warp] = s;
        __syncthreads();
        if (warp == 0) {
            int w = wsum[lane];
#pragma unroll
            for (int off = 1; off < 32; off <<= 1) {
                int t = __shfl_up_sync(0xFFFFFFFFu, w, off);
                if (lane >= off) w += t;
            }
            wsum[lane] = w;
        }
        __syncthreads();
        int off = carry + (warp ? wsum[warp - 1] : 0);
        if (i < NN) {
            g_rowptr[i] = off + s - v;
            g_invdeg[i] = 1.0f / (float)(v > 1 ? v : 1);
            g_deg[i] = 0;                          // reuse as fill cursor
            int b = batch[i];
            if (i == 0 || batch[i - 1] != b) g_root[b] = i;
        }
        __syncthreads();
        if (tid == 0) carry += wsum[31];
        __syncthreads();
    }
    if (tid == 0) g_rowptr[NN] = carry;
}

__global__ void k_fill(const int* __restrict__ src, const int* __restrict__ dst) {
    int e = blockIdx.x * blockDim.x + threadIdx.x;
    if (e < EE) {
        int d = dst[e];
        int pos = g_rowptr[d] + atomicAdd(&g_deg[d], 1);
        g_col[pos] = src[e];
    }
}

// W^T hi/lo split for all 3 layers, frag-packed
__global__ void k_prep_w(const float* __restrict__ Wl1, const float* __restrict__ Wr1,
                         const float* __restrict__ Wl2, const float* __restrict__ Wr2,
                         const float* __restrict__ Wl3, const float* __restrict__ Wr3) {
    int gidx = blockIdx.x * blockDim.x + threadIdx.x;
    const int PER = DD * KK / 2;                    // 16384 pairs per layer
    int layer = gidx / PER;
    if (layer >= 3) return;
    int idx = gidx - layer * PER;
    const float* Wl = layer == 0 ? Wl1 : (layer == 1 ? Wl2 : Wl3);
    const float* Wr = layer == 0 ? Wr1 : (layer == 1 ? Wr2 : Wr3);
    int n = idx >> 7;
    int kp = (idx & 127) * 2;
    float w0 = (kp < 128) ? Wl[kp * 128 + n] : Wr[(kp - 128) * 128 + n];
    int k1 = kp + 1;
    float w1 = (k1 < 128) ? Wl[k1 * 128 + n] : Wr[(k1 - 128) * 128 + n];
    uint32_t hi, lo;
    split2(w0, w1, hi, lo);
    int pidx = pk_idx(kp >> 1);
    g_Whi[layer][n * 128 + pidx] = hi;
    g_Wlo[layer][n * 128 + pidx] = lo;
}

// ---------------- HMMA helper ----------------
__device__ __forceinline__ void mma16816(float* c, const uint32_t* a, const uint32_t* b) {
    asm volatile(
        "mma.sync.aligned.m16n8k16.row.col.f32.bf16.bf16.f32 "
        "{%0,%1,%2,%3}, {%4,%5,%6,%7}, {%8,%9}, {%0,%1,%2,%3};"
        : "+f"(c[0]), "+f"(c[1]), "+f"(c[2]), "+f"(c[3])
        : "r"(a[0]), "r"(a[1]), "r"(a[2]), "r"(a[3]), "r"(b[0]), "r"(b[1]));
}

// ---------------- fused layer: phase1 = mean-agg (+ x-split) for own 128 rows,
//                  phase2 = HMMA GEMM h = relu(A @ W^T + b) ----------------
__global__ void __launch_bounds__(256) k_layer(const float* __restrict__ ext_in,
                                               int in_sel, int do_x,
                                               const float* __restrict__ bl,
                                               int layer, int out_sel, int write_split) {
    int tid = threadIdx.x;
    int wid = tid >> 5;
    int lane = tid & 31;
    int block_m = blockIdx.x * TM;

    // ---------- phase 1: aggregate nodes block_m + wid*16 .. +15 ----------
    {
        const float* hin = (in_sel < 0) ? ext_in : hbuf(in_sel);
        int p0 = lane * 2, p1 = lane * 2 + 1;
        int i0 = pk_idx(p0), i1 = pk_idx(p1);
        int j0 = pk_idx(64 + p0), j1 = pk_idx(64 + p1);
#pragma unroll 1
        for (int j = 0; j < 16; ++j) {
            int node = block_m + wid * 16 + j;
            if (node >= NN) break;
            int s = g_rowptr[node];
            int e = g_rowptr[node + 1];
            float4 a0 = make_float4(0.f, 0.f, 0.f, 0.f);
            float4 a1 = a0, a2 = a0, a3 = a0;
            int i = s;
            for (; i + 4 <= e; i += 4) {
                int c0 = g_col[i], c1 = g_col[i + 1], c2 = g_col[i + 2], c3 = g_col[i + 3];
                float4 v0 = *(const float4*)(hin + (size_t)c0 * DD + lane * 4);
                float4 v1 = *(const float4*)(hin + (size_t)c1 * DD + lane * 4);
                float4 v2 = *(const float4*)(hin + (size_t)c2 * DD + lane * 4);
                float4 v3 = *(const float4*)(hin + (size_t)c3 * DD + lane * 4);
                a0.x += v0.x; a0.y += v0.y; a0.z += v0.z; a0.w += v0.w;
                a1.x += v1.x; a1.y += v1.y; a1.z += v1.z; a1.w += v1.w;
                a2.x += v2.x; a2.y += v2.y; a2.z += v2.z; a2.w += v2.w;
                a3.x += v3.x; a3.y += v3.y; a3.z += v3.z; a3.w += v3.w;
            }
            for (; i < e; ++i) {
                int c0 = g_col[i];
                float4 v0 = *(const float4*)(hin + (size_t)c0 * DD + lane * 4);
                a0.x += v0.x; a0.y += v0.y; a0.z += v0.z; a0.w += v0.w;
            }
            float iv = g_invdeg[node];
            float4 m;
            m.x = (a0.x + a1.x + a2.x + a3.x) * iv;
            m.y = (a0.y + a1.y + a2.y + a3.y) * iv;
            m.z = (a0.z + a1.z + a2.z + a3.z) * iv;
            m.w = (a0.w + a1.w + a2.w + a3.w) * iv;
            uint32_t h0, l0, h1, l1;
            split2(m.x, m.y, h0, l0);
            split2(m.z, m.w, h1, l1);
            uint32_t* rh = g_Ahi + (size_t)node * 128;
            uint32_t* rl = g_Alo + (size_t)node * 128;
            rh[i0] = h0; rh[i1] = h1;
            rl[i0] = l0; rl[i1] = l1;
            if (do_x) {   // layer 1: also split own x row into cols 128:256
                float4 xv = *(const float4*)(ext_in + (size_t)node * DD + lane * 4);
                split2(xv.x, xv.y, h0, l0);
                split2(xv.z, xv.w, h1, l1);
                rh[j0] = h0; rh[j1] = h1;
                rl[j0] = l0; rl[j1] = l1;
            }
        }
    }
    __syncthreads();   // block's own rows' A now visible (global ordering within block)

    // ---------- phase 2: GEMM ----------
    int wm = wid & 3;
    int wn = wid >> 2;
    const uint32_t* Bh = g_Whi[layer];
    const uint32_t* Bl = g_Wlo[layer];
    int grp = lane >> 2;
    int quad = lane & 3;

    int arow[2][2];
#pragma unroll
    for (int mi = 0; mi < 2; ++mi) {
        int r0 = block_m + wm * 32 + mi * 16 + grp;
        int r1 = r0 + 8;
        arow[mi][0] = r0 < NN ? r0 : NN - 1;
        arow[mi][1] = r1 < NN ? r1 : NN - 1;
    }
    int brow[8];
#pragma unroll
    for (int ni = 0; ni < 8; ++ni) brow[ni] = wn * 64 + ni * 8 + grp;

    float acc[2][8][4];
#pragma unroll
    for (int mi = 0; mi < 2; ++mi)
#pragma unroll
        for (int ni = 0; ni < 8; ++ni)
#pragma unroll
            for (int r = 0; r < 4; ++r) acc[mi][ni][r] = 0.f;

#pragma unroll 4
    for (int kg = 0; kg < 16; ++kg) {
        int go = kg * 8 + quad * 2;     // packed uint32 offset within row
        uint32_t ah[2][4], al[2][4];
#pragma unroll
        for (int mi = 0; mi < 2; ++mi) {
            uint2 h0 = *(const uint2*)(g_Ahi + (size_t)arow[mi][0] * 128 + go);
            uint2 h1 = *(const uint2*)(g_Ahi + (size_t)arow[mi][1] * 128 + go);
            ah[mi][0] = h0.x; ah[mi][1] = h1.x; ah[mi][2] = h0.y; ah[mi][3] = h1.y;
            uint2 q0 = *(const uint2*)(g_Alo + (size_t)arow[mi][0] * 128 + go);
            uint2 q1 = *(const uint2*)(g_Alo + (size_t)arow[mi][1] * 128 + go);
            al[mi][0] = q0.x; al[mi][1] = q1.x; al[mi][2] = q0.y; al[mi][3] = q1.y;
        }
        uint32_t bh[8][2], blo[8][2];
#pragma unroll
        for (int ni = 0; ni < 8; ++ni) {
            uint2 b0 = *(const uint2*)(Bh + (size_t)brow[ni] * 128 + go);
            bh[ni][0] = b0.x; bh[ni][1] = b0.y;
            uint2 b1 = *(const uint2*)(Bl + (size_t)brow[ni] * 128 + go);
            blo[ni][0] = b1.x; blo[ni][1] = b1.y;
        }
#pragma unroll
        for (int mi = 0; mi < 2; ++mi)
#pragma unroll
            for (int ni = 0; ni < 8; ++ni) {
                mma16816(acc[mi][ni], ah[mi], bh[ni]);
                mma16816(acc[mi][ni], ah[mi], blo[ni]);
                mma16816(acc[mi][ni], al[mi], bh[ni]);
            }
    }

    // epilogue: fp32 h + optional frag-packed bf16 split of h into cols 128:256
    float* outp = hbuf(out_sel);
#pragma unroll
    for (int mi = 0; mi < 2; ++mi) {
        int r0 = block_m + wm * 32 + mi * 16 + grp;
#pragma unroll
        for (int ni = 0; ni < 8; ++ni) {
            int col = wn * 64 + ni * 8 + quad * 2;
            float b0 = bl[col], b1 = bl[col + 1];
            int pidx = pk_idx(64 + (col >> 1));
            if (r0 < NN) {
                float2 v;
                v.x = fmaxf(acc[mi][ni][0] + b0, 0.f);
                v.y = fmaxf(acc[mi][ni][1] + b1, 0.f);
                *(float2*)(outp + (size_t)r0 * DD + col) = v;
                if (write_split) {
                    uint32_t hi, lo;
                    split2(v.x, v.y, hi, lo);
                    g_Ahi[(size_t)r0 * 128 + pidx] = hi;
                    g_Alo[(size_t)r0 * 128 + pidx] = lo;
                }
            }
            if (r0 + 8 < NN) {
                float2 v;
                v.x = fmaxf(acc[mi][ni][2] + b0, 0.f);
                v.y = fmaxf(acc[mi][ni][3] + b1, 0.f);
                *(float2*)(outp + (size_t)(r0 + 8) * DD + col) = v;
                if (write_split) {
                    uint32_t hi, lo;
                    split2(v.x, v.y, hi, lo);
                    g_Ahi[(size_t)(r0 + 8) * 128 + pidx] = hi;
                    g_Alo[(size_t)(r0 + 8) * 128 + pidx] = lo;
                }
            }
        }
    }
}

// ---------------- pooling: 128 threads per block, 64 nodes, flush on graph change ----------------
#define POOL_NODES 64
__global__ void __launch_bounds__(128) k_pool2(const int* __restrict__ batch) {
    int n0 = blockIdx.x * POOL_NODES;
    int col = threadIdx.x;
    if (n0 >= NN) return;
    int nend = n0 + POOL_NODES; if (nend > NN) nend = NN;
    int cur = batch[n0];
    float m = 0.f;
    for (int n = n0; n < nend; ++n) {
        int b = batch[n];
        if (b != cur) {
            atomicMax((int*)g_pool + (size_t)cur * DD + col, __float_as_int(m));
            m = 0.f;
            cur = b;
        }
        m = fmaxf(m, g_h1[(size_t)n * DD + col]);
    }
    atomicMax((int*)g_pool + (size_t)cur * DD + col, __float_as_int(m));
}

// ---------------- per-graph MLP head ----------------
__global__ void __launch_bounds__(256) k_head(const float* __restrict__ x,
                                              const float* __restrict__ Wf1, const float* __restrict__ bf1,
                                              const float* __restrict__ Wf2, const float* __restrict__ bf2,
                                              const float* __restrict__ Wsm, const float* __restrict__ bsm,
                                              const float* __restrict__ Wnews, const float* __restrict__ bnews,
                                              const float* __restrict__ Wcat, const float* __restrict__ bcat,
                                              float* __restrict__ out) {
    int b = blockIdx.x;
    int t = threadIdx.x;
    __shared__ float p[128], xr[128], t1[256], t2[128], sres[4];
    if (t < 128) {
        p[t] = g_pool[(size_t)b * DD + t];
        xr[t] = x[(size_t)g_root[b] * DD + t];
    }
    __syncthreads();
    {
        float acc = bf1[t];
#pragma unroll 4
        for (int k = 0; k < 128; k++) acc += p[k] * Wf1[k * 256 + t];
        t1[t] = fmaxf(acc, 0.f);
    }
    __syncthreads();
    if (t < 128) {
        float acc = bf2[t];
#pragma unroll 4
        for (int k = 0; k < 256; k++) acc += t1[k] * Wf2[k * 128 + t];
        t2[t] = fmaxf(acc, 0.f);
    }
    __syncthreads();
    if (t < 2) {
        float acc = bsm[t];
        for (int k = 0; k < 128; k++) acc += t2[k] * Wsm[k * 2 + t];
        sres[t] = fmaxf(acc, 0.f);
        float a2 = bnews[t];
        for (int k = 0; k < 128; k++) a2 += xr[k] * Wnews[k * 2 + t];
        sres[2 + t] = fmaxf(a2, 0.f);
    }
    __syncthreads();
    if (t == 0) {
        float o = bcat[0];
        for (int k = 0; k < 4; k++) o += sres[k] * Wcat[k];
        out[b] = 1.f / (1.f + expf(-o));
    }
}

// ---------------- launch ----------------
extern "C" void kernel_launch(void* const* d_in, const int* in_sizes, int n_in,
                              void* d_out, int out_size) {
    const float* x     = (const float*)d_in[0];
    const int*   ei    = (const int*)d_in[1];
    const int*   src   = ei;
    const int*   dst   = ei + EE;
    const int*   batch = (const int*)d_in[2];
    const float* Wl1 = (const float*)d_in[3];
    const float* Wr1 = (const float*)d_in[4];
    const float* bl1 = (const float*)d_in[5];
    const float* Wl2 = (const float*)d_in[6];
    const float* Wr2 = (const float*)d_in[7];
    const float* bl2 = (const float*)d_in[8];
    const float* Wl3 = (const float*)d_in[9];
    const float* Wr3 = (const float*)d_in[10];
    const float* bl3 = (const float*)d_in[11];
    const float* Wf1 = (const float*)d_in[12];
    const float* bf1 = (const float*)d_in[13];
    const float* Wf2 = (const float*)d_in[14];
    const float* bf2 = (const float*)d_in[15];
    const float* Wsm = (const float*)d_in[16];
    const float* bsm = (const float*)d_in[17];
    const float* Wnews = (const float*)d_in[18];
    const float* bnews = (const float*)d_in[19];
    const float* Wcat = (const float*)d_in[20];
    const float* bcat = (const float*)d_in[21];
    float* out = (float*)d_out;

    const int TB = 256;
    int gE = (EE + TB - 1) / TB;
    int gPrep = (3 * DD * KK / 2 + TB - 1) / TB;

    k_init<<<256, TB>>>();                       // 1
    k_count<<<gE, TB>>>(dst);                    // 2
    k_scan_fused<<<1, 1024>>>(batch);            // 3
    k_fill<<<gE, TB>>>(src, dst);                // 4  <- profiled launch
    k_prep_w<<<gPrep, TB>>>(Wl1, Wr1, Wl2, Wr2, Wl3, Wr3);   // 5

    // fused agg+GEMM layers
    k_layer<<<GEMM_BLOCKS, 256>>>(x, -1, 1, bl1, 0, 1, 1);        // 6
    k_layer<<<GEMM_BLOCKS, 256>>>(nullptr, 1, 0, bl2, 1, 2, 1);   // 7
    k_layer<<<GEMM_BLOCKS, 256>>>(nullptr, 2, 0, bl3, 2, 1, 0);   // 8

    k_pool2<<<(NN + POOL_NODES - 1) / POOL_NODES, 128>>>(batch);  // 9
    k_head<<<BB, TB>>>(x, Wf1, bf1, Wf2, bf2, Wsm, bsm, Wnews, bnews, Wcat, bcat, out);  // 10
}

// round 10
// speedup vs baseline: 1.6702x; 1.6702x over previous
#include <cuda_runtime.h>
#include <cuda_bf16.h>
#include <math.h>
#include <stdint.h>

#define NN 50000
#define EE 800000
#define BB 512
#define DD 128
#define KK 256
#define TM 128
#define GEMM_BLOCKS ((NN + TM - 1) / TM)   // 391

// ---------------- scratch (static device globals; no allocation) ----------------
__device__ float g_h1[NN * DD];               // layer-3 output (for pooling)
// frag-packed bf16 operand storage: per row, 128 uint32.
// slots 0..63  = aggregation result (cols 0..127 of A)
// slots 64..127 = h/x split (cols 128..255 of A)
// within each 8-slot group (16 cols): pair p (pg=p&7) sits at slot ((pg&3)<<1)+(pg>>2)
__device__ uint32_t g_Ahi[NN * 128];
__device__ uint32_t g_Alo[NN * 128];
// W^T packed as uint4 {hi(pair kg*8+q), hi(pair kg*8+q+4), lo(..), lo(..)} at [n*64 + kg*4 + q]
__device__ uint4 g_W[3][DD * 64];
__device__ float g_pool[BB * DD];
__device__ float g_invdeg[NN];
__device__ int   g_deg[NN];
__device__ int   g_rowptr[NN + 1];
__device__ int   g_col[EE];
__device__ int   g_root[BB];

// packed slot index for pair (0..127)
__device__ __forceinline__ int pk_idx(int pair) {
    int g = pair >> 3, pg = pair & 7;
    return g * 8 + ((pg & 3) << 1) + (pg >> 2);
}

// bf16x2 unpack via bit ops (bf16 -> fp32 is a 16-bit shift)
__device__ __forceinline__ float bf_lo(uint32_t u) { return __uint_as_float(u << 16); }
__device__ __forceinline__ float bf_hi(uint32_t u) { return __uint_as_float(u & 0xFFFF0000u); }

// ---------------- fp32 -> bf16 hi/lo split ----------------
__device__ __forceinline__ void split2(float a, float b, uint32_t& hi, uint32_t& lo) {
    __nv_bfloat16 ha = __float2bfloat16(a);
    __nv_bfloat16 hb = __float2bfloat16(b);
    __nv_bfloat16 la = __float2bfloat16(a - __bfloat162float(ha));
    __nv_bfloat16 lb = __float2bfloat16(b - __bfloat162float(hb));
    hi = ((uint32_t)__bfloat16_as_ushort(hb) << 16) | __bfloat16_as_ushort(ha);
    lo = ((uint32_t)__bfloat16_as_ushort(lb) << 16) | __bfloat16_as_ushort(la);
}

// ---------------- init: zero deg + pool ----------------
__global__ void k_init() {
    int i = blockIdx.x * blockDim.x + threadIdx.x;
    if (i < NN) g_deg[i] = 0;
    if (i < BB * DD) ((int*)g_pool)[i] = 0;          // 0 bits == +0.0f
}

__global__ void k_count(const int* __restrict__ dst) {
    int e = blockIdx.x * blockDim.x + threadIdx.x;
    if (e < EE) atomicAdd(&g_deg[dst[e]], 1);
}

// exclusive scan + invdeg + cursor reset + roots, single block
__global__ void k_scan_fused(const int* __restrict__ batch) {
    __shared__ int wsum[32];
    __shared__ int carry;
    int tid = threadIdx.x;
    int warp = tid >> 5, lane = tid & 31;
    if (tid == 0) carry = 0;
    __syncthreads();
    for (int base = 0; base < NN; base += 1024) {
        int i = base + tid;
        int v = (i < NN) ? g_deg[i] : 0;
        int s = v;
#pragma unroll
        for (int off = 1; off < 32; off <<= 1) {
            int t = __shfl_up_sync(0xFFFFFFFFu, s, off);
            if (lane >= off) s += t;
        }
        if (lane == 31) wsum[warp] = s;
        __syncthreads();
        if (warp == 0) {
            int w = wsum[lane];
#pragma unroll
            for (int off = 1; off < 32; off <<= 1) {
                int t = __shfl_up_sync(0xFFFFFFFFu, w, off);
                if (lane >= off) w += t;
            }
            wsum[lane] = w;
        }
        __syncthreads();
        int off = carry + (warp ? wsum[warp - 1] : 0);
        if (i < NN) {
            g_rowptr[i] = off + s - v;
            g_invdeg[i] = 1.0f / (float)(v > 1 ? v : 1);
            g_deg[i] = 0;                          // reuse as fill cursor
            int b = batch[i];
            if (i == 0 || batch[i - 1] != b) g_root[b] = i;
        }
        __syncthreads();
        if (tid == 0) carry += wsum[31];
        __syncthreads();
    }
    if (tid == 0) g_rowptr[NN] = carry;
}

__global__ void k_fill(const int* __restrict__ src, const int* __restrict__ dst) {
    int e = blockIdx.x * blockDim.x + threadIdx.x;
    if (e < EE) {
        int d = dst[e];
        int pos = g_rowptr[d] + atomicAdd(&g_deg[d], 1);
        g_col[pos] = src[e];
    }
}

// W^T hi/lo split for all 3 layers, uint4-frag-packed
// thread -> (layer, n, g) with g = kg*4 + q; covers cols kc0,kc0+1,kc0+8,kc0+9
__global__ void k_prep_w(const float* __restrict__ Wl1, const float* __restrict__ Wr1,
                         const float* __restrict__ Wl2, const float* __restrict__ Wr2,
                         const float* __restrict__ Wl3, const float* __restrict__ Wr3) {
    int gidx = blockIdx.x * blockDim.x + threadIdx.x;
    const int PER = DD * 64;                    // 8192 uint4 per layer
    int layer = gidx / PER;
    if (layer >= 3) return;
    int idx = gidx - layer * PER;
    const float* Wl = layer == 0 ? Wl1 : (layer == 1 ? Wl2 : Wl3);
    const float* Wr = layer == 0 ? Wr1 : (layer == 1 ? Wr2 : Wr3);
    int n = idx >> 6;            // 0..127
    int g = idx & 63;            // kg*4 + q
    int kg = g >> 2, q = g & 3;
    int kc0 = kg * 16 + q * 2;
    float w[4];
#pragma unroll
    for (int t = 0; t < 4; ++t) {
        int col = kc0 + (t >> 1) * 8 + (t & 1);
        w[t] = (col < 128) ? Wl[col * 128 + n] : Wr[(col - 128) * 128 + n];
    }
    uint4 v;
    split2(w[0], w[1], v.x, v.z);
    split2(w[2], w[3], v.y, v.w);
    g_W[layer][n * 64 + g] = v;
}

// ---------------- mean aggregation: warp per node ----------------
// lane -> (kg = lane>>2, q = lane&3); owns cols c0,c0+1,c0+8,c0+9 with c0 = kg*16+q*2
// input: fp32 x (layer 1) or bf16 split h-region (layers 2,3)
// output: split into agg region slots (kg*8+2q, +1); do_x also fills h-region with x split
__global__ void __launch_bounds__(256) k_agg(const float* __restrict__ x,
                                             int use_split, int do_x) {
    int warp = (blockIdx.x * blockDim.x + threadIdx.x) >> 5;
    int lane = threadIdx.x & 31;
    if (warp >= NN) return;
    int kg = lane >> 2, q = lane & 3;
    int c0 = kg * 16 + q * 2;
    int slot = kg * 8 + 2 * q;                 // pk slot pair base
    int s = g_rowptr[warp];
    int e = g_rowptr[warp + 1];
    float a0 = 0.f, a1 = 0.f, a2 = 0.f, a3 = 0.f;     // chain 0
    float b0 = 0.f, b1 = 0.f, b2 = 0.f, b3 = 0.f;     // chain 1
    float c0f = 0.f, c1f = 0.f, c2f = 0.f, c3f = 0.f; // chain 2
    float d0 = 0.f, d1 = 0.f, d2 = 0.f, d3 = 0.f;     // chain 3
    int i = s;
    if (use_split) {
        const uint32_t* Hh = g_Ahi;
        const uint32_t* Hl = g_Alo;
        int off = 64 + slot;
        for (; i + 4 <= e; i += 4) {
            int n0 = g_col[i], n1 = g_col[i + 1], n2 = g_col[i + 2], n3 = g_col[i + 3];
            uint2 h0 = *(const uint2*)(Hh + (size_t)n0 * 128 + off);
            uint2 l0 = *(const uint2*)(Hl + (size_t)n0 * 128 + off);
            uint2 h1 = *(const uint2*)(Hh + (size_t)n1 * 128 + off);
            uint2 l1 = *(const uint2*)(Hl + (size_t)n1 * 128 + off);
            uint2 h2 = *(const uint2*)(Hh + (size_t)n2 * 128 + off);
            uint2 l2 = *(const uint2*)(Hl + (size_t)n2 * 128 + off);
            uint2 h3 = *(const uint2*)(Hh + (size_t)n3 * 128 + off);
            uint2 l3 = *(const uint2*)(Hl + (size_t)n3 * 128 + off);
            a0 += bf_lo(h0.x) + bf_lo(l0.x); a1 += bf_hi(h0.x) + bf_hi(l0.x);
            a2 += bf_lo(h0.y) + bf_lo(l0.y); a3 += bf_hi(h0.y) + bf_hi(l0.y);
            b0 += bf_lo(h1.x) + bf_lo(l1.x); b1 += bf_hi(h1.x) + bf_hi(l1.x);
            b2 += bf_lo(h1.y) + bf_lo(l1.y); b3 += bf_hi(h1.y) + bf_hi(l1.y);
            c0f += bf_lo(h2.x) + bf_lo(l2.x); c1f += bf_hi(h2.x) + bf_hi(l2.x);
            c2f += bf_lo(h2.y) + bf_lo(l2.y); c3f += bf_hi(h2.y) + bf_hi(l2.y);
            d0 += bf_lo(h3.x) + bf_lo(l3.x); d1 += bf_hi(h3.x) + bf_hi(l3.x);
            d2 += bf_lo(h3.y) + bf_lo(l3.y); d3 += bf_hi(h3.y) + bf_hi(l3.y);
        }
        for (; i < e; ++i) {
            int n0 = g_col[i];
            uint2 h0 = *(const uint2*)(Hh + (size_t)n0 * 128 + off);
            uint2 l0 = *(const uint2*)(Hl + (size_t)n0 * 128 + off);
            a0 += bf_lo(h0.x) + bf_lo(l0.x); a1 += bf_hi(h0.x) + bf_hi(l0.x);
            a2 += bf_lo(h0.y) + bf_lo(l0.y); a3 += bf_hi(h0.y) + bf_hi(l0.y);
        }
    } else {
        for (; i + 4 <= e; i += 4) {
            int n0 = g_col[i], n1 = g_col[i + 1], n2 = g_col[i + 2], n3 = g_col[i + 3];
            float2 u0 = *(const float2*)(x + (size_t)n0 * DD + c0);
            float2 v0 = *(const float2*)(x + (size_t)n0 * DD + c0 + 8);
            float2 u1 = *(const float2*)(x + (size_t)n1 * DD + c0);
            float2 v1 = *(const float2*)(x + (size_t)n1 * DD + c0 + 8);
            float2 u2 = *(const float2*)(x + (size_t)n2 * DD + c0);
            float2 v2 = *(const float2*)(x + (size_t)n2 * DD + c0 + 8);
            float2 u3 = *(const float2*)(x + (size_t)n3 * DD + c0);
            float2 v3 = *(const float2*)(x + (size_t)n3 * DD + c0 + 8);
            a0 += u0.x; a1 += u0.y; a2 += v0.x; a3 += v0.y;
            b0 += u1.x; b1 += u1.y; b2 += v1.x; b3 += v1.y;
            c0f += u2.x; c1f += u2.y; c2f += v2.x; c3f += v2.y;
            d0 += u3.x; d1 += u3.y; d2 += v3.x; d3 += v3.y;
        }
        for (; i < e; ++i) {
            int n0 = g_col[i];
            float2 u0 = *(const float2*)(x + (size_t)n0 * DD + c0);
            float2 v0 = *(const float2*)(x + (size_t)n0 * DD + c0 + 8);
            a0 += u0.x; a1 += u0.y; a2 += v0.x; a3 += v0.y;
        }
    }
    float iv = g_invdeg[warp];
    float m0 = (a0 + b0 + c0f + d0) * iv;
    float m1 = (a1 + b1 + c1f + d1) * iv;
    float m2 = (a2 + b2 + c2f + d2) * iv;
    float m3 = (a3 + b3 + c3f + d3) * iv;
    uint32_t ha, la, hb, lb;
    split2(m0, m1, ha, la);
    split2(m2, m3, hb, lb);
    *(uint2*)(g_Ahi + (size_t)warp * 128 + slot) = make_uint2(ha, hb);
    *(uint2*)(g_Alo + (size_t)warp * 128 + slot) = make_uint2(la, lb);
    if (do_x) {   // layer 1: also split own x row into h-region
        float2 u = *(const float2*)(x + (size_t)warp * DD + c0);
        float2 v = *(const float2*)(x + (size_t)warp * DD + c0 + 8);
        split2(u.x, u.y, ha, la);
        split2(v.x, v.y, hb, lb);
        *(uint2*)(g_Ahi + (size_t)warp * 128 + 64 + slot) = make_uint2(ha, hb);
        *(uint2*)(g_Alo + (size_t)warp * 128 + 64 + slot) = make_uint2(la, lb);
    }
}

// ---------------- HMMA helper ----------------
__device__ __forceinline__ void mma16816(float* c, const uint32_t* a, const uint32_t* b) {
    asm volatile(
        "mma.sync.aligned.m16n8k16.row.col.f32.bf16.bf16.f32 "
        "{%0,%1,%2,%3}, {%4,%5,%6,%7}, {%8,%9}, {%0,%1,%2,%3};"
        : "+f"(c[0]), "+f"(c[1]), "+f"(c[2]), "+f"(c[3])
        : "r"(a[0]), "r"(a[1]), "r"(a[2]), "r"(a[3]), "r"(b[0]), "r"(b[1]));
}

// ---------------- HMMA GEMM: h = relu(A @ W^T + b) ----------------
// write_mode: 1 = write bf16 split into h-region (layers 1,2); 0 = write fp32 g_h1 (layer 3)
__global__ void __launch_bounds__(256) k_gemm_hmma(const float* __restrict__ bl,
                                                   int layer, int write_mode) {
    int tid = threadIdx.x;
    int wid = tid >> 5;
    int lane = tid & 31;
    int wm = wid & 3;
    int wn = wid >> 2;
    int block_m = blockIdx.x * TM;

    const uint4* W = g_W[layer];
    int grp = lane >> 2;
    int quad = lane & 3;

    int arow[2][2];
#pragma unroll
    for (int mi = 0; mi < 2; ++mi) {
        int r0 = block_m + wm * 32 + mi * 16 + grp;
        int r1 = r0 + 8;
        arow[mi][0] = r0 < NN ? r0 : NN - 1;
        arow[mi][1] = r1 < NN ? r1 : NN - 1;
    }
    int brow[8];
#pragma unroll
    for (int ni = 0; ni < 8; ++ni) brow[ni] = wn * 64 + ni * 8 + grp;

    float acc[2][8][4];
#pragma unroll
    for (int mi = 0; mi < 2; ++mi)
#pragma unroll
        for (int ni = 0; ni < 8; ++ni)
#pragma unroll
            for (int r = 0; r < 4; ++r) acc[mi][ni][r] = 0.f;

#pragma unroll 4
    for (int kg = 0; kg < 16; ++kg) {
        int go = kg * 8 + quad * 2;     // packed uint32 offset within A row
        uint32_t ah[2][4], al[2][4];
#pragma unroll
        for (int mi = 0; mi < 2; ++mi) {
            uint2 h0 = *(const uint2*)(g_Ahi + (size_t)arow[mi][0] * 128 + go);
            uint2 h1 = *(const uint2*)(g_Ahi + (size_t)arow[mi][1] * 128 + go);
            ah[mi][0] = h0.x; ah[mi][1] = h1.x; ah[mi][2] = h0.y; ah[mi][3] = h1.y;
            uint2 q0 = *(const uint2*)(g_Alo + (size_t)arow[mi][0] * 128 + go);
            uint2 q1 = *(const uint2*)(g_Alo + (size_t)arow[mi][1] * 128 + go);
            al[mi][0] = q0.x; al[mi][1] = q1.x; al[mi][2] = q0.y; al[mi][3] = q1.y;
        }
        uint32_t bh[8][2], blo[8][2];
#pragma unroll
        for (int ni = 0; ni < 8; ++ni) {
            uint4 v = W[brow[ni] * 64 + kg * 4 + quad];
            bh[ni][0] = v.x; bh[ni][1] = v.y;
            blo[ni][0] = v.z; blo[ni][1] = v.w;
        }
#pragma unroll
        for (int mi = 0; mi < 2; ++mi)
#pragma unroll
            for (int ni = 0; ni < 8; ++ni) {
                mma16816(acc[mi][ni], ah[mi], bh[ni]);
                mma16816(acc[mi][ni], ah[mi], blo[ni]);
                mma16816(acc[mi][ni], al[mi], bh[ni]);
            }
    }

    // epilogue
#pragma unroll
    for (int mi = 0; mi < 2; ++mi) {
        int r0 = block_m + wm * 32 + mi * 16 + grp;
#pragma unroll
        for (int ni = 0; ni < 8; ++ni) {
            int col = wn * 64 + ni * 8 + quad * 2;
            float b0 = bl[col], b1 = bl[col + 1];
            int pidx = pk_idx(64 + (col >> 1));
#pragma unroll
            for (int h = 0; h < 2; ++h) {
                int r = r0 + h * 8;
                if (r >= NN) continue;
                float vx = fmaxf(acc[mi][ni][h * 2 + 0] + b0, 0.f);
                float vy = fmaxf(acc[mi][ni][h * 2 + 1] + b1, 0.f);
                if (write_mode) {
                    uint32_t hi, lo;
                    split2(vx, vy, hi, lo);
                    g_Ahi[(size_t)r * 128 + pidx] = hi;
                    g_Alo[(size_t)r * 128 + pidx] = lo;
                } else {
                    *(float2*)(g_h1 + (size_t)r * DD + col) = make_float2(vx, vy);
                }
            }
        }
    }
}

// ---------------- pooling: 128 threads per block, 64 nodes, flush on graph change ----------------
#define POOL_NODES 64
__global__ void __launch_bounds__(128) k_pool2(const int* __restrict__ batch) {
    int n0 = blockIdx.x * POOL_NODES;
    int col = threadIdx.x;
    if (n0 >= NN) return;
    int nend = n0 + POOL_NODES; if (nend > NN) nend = NN;
    int cur = batch[n0];
    float m = 0.f;
    for (int n = n0; n < nend; ++n) {
        int b = batch[n];
        if (b != cur) {
            atomicMax((int*)g_pool + (size_t)cur * DD + col, __float_as_int(m));
            m = 0.f;
            cur = b;
        }
        m = fmaxf(m, g_h1[(size_t)n * DD + col]);
    }
    atomicMax((int*)g_pool + (size_t)cur * DD + col, __float_as_int(m));
}

// ---------------- per-graph MLP head ----------------
__global__ void __launch_bounds__(256) k_head(const float* __restrict__ x,
                                              const float* __restrict__ Wf1, const float* __restrict__ bf1,
                                              const float* __restrict__ Wf2, const float* __restrict__ bf2,
                                              const float* __restrict__ Wsm, const float* __restrict__ bsm,
                                              const float* __restrict__ Wnews, const float* __restrict__ bnews,
                                              const float* __restrict__ Wcat, const float* __restrict__ bcat,
                                              float* __restrict__ out) {
    int b = blockIdx.x;
    int t = threadIdx.x;
    __shared__ float p[128], xr[128], t1[256], t2[128], sres[4];
    if (t < 128) {
        p[t] = g_pool[(size_t)b * DD + t];
        xr[t] = x[(size_t)g_root[b] * DD + t];
    }
    __syncthreads();
    {
        float acc = bf1[t];
#pragma unroll 4
        for (int k = 0; k < 128; k++) acc += p[k] * Wf1[k * 256 + t];
        t1[t] = fmaxf(acc, 0.f);
    }
    __syncthreads();
    if (t < 128) {
        float acc = bf2[t];
#pragma unroll 4
        for (int k = 0; k < 256; k++) acc += t1[k] * Wf2[k * 128 + t];
        t2[t] = fmaxf(acc, 0.f);
    }
    __syncthreads();
    if (t < 2) {
        float acc = bsm[t];
        for (int k = 0; k < 128; k++) acc += t2[k] * Wsm[k * 2 + t];
        sres[t] = fmaxf(acc, 0.f);
        float a2 = bnews[t];
        for (int k = 0; k < 128; k++) a2 += xr[k] * Wnews[k * 2 + t];
        sres[2 + t] = fmaxf(a2, 0.f);
    }
    __syncthreads();
    if (t == 0) {
        float o = bcat[0];
        for (int k = 0; k < 4; k++) o += sres[k] * Wcat[k];
        out[b] = 1.f / (1.f + expf(-o));
    }
}

// ---------------- launch ----------------
extern "C" void kernel_launch(void* const* d_in, const int* in_sizes, int n_in,
                              void* d_out, int out_size) {
    const float* x     = (const float*)d_in[0];
    const int*   ei    = (const int*)d_in[1];
    const int*   src   = ei;
    const int*   dst   = ei + EE;
    const int*   batch = (const int*)d_in[2];
    const float* Wl1 = (const float*)d_in[3];
    const float* Wr1 = (const float*)d_in[4];
    const float* bl1 = (const float*)d_in[5];
    const float* Wl2 = (const float*)d_in[6];
    const float* Wr2 = (const float*)d_in[7];
    const float* bl2 = (const float*)d_in[8];
    const float* Wl3 = (const float*)d_in[9];
    const float* Wr3 = (const float*)d_in[10];
    const float* bl3 = (const float*)d_in[11];
    const float* Wf1 = (const float*)d_in[12];
    const float* bf1 = (const float*)d_in[13];
    const float* Wf2 = (const float*)d_in[14];
    const float* bf2 = (const float*)d_in[15];
    const float* Wsm = (const float*)d_in[16];
    const float* bsm = (const float*)d_in[17];
    const float* Wnews = (const float*)d_in[18];
    const float* bnews = (const float*)d_in[19];
    const float* Wcat = (const float*)d_in[20];
    const float* bcat = (const float*)d_in[21];
    float* out = (float*)d_out;

    const int TB = 256;
    int gE = (EE + TB - 1) / TB;
    int gWarpN = (NN * 32 + TB - 1) / TB;
    int gPrep = (3 * DD * 64 + TB - 1) / TB;

    k_init<<<256, TB>>>();                       // 1
    k_count<<<gE, TB>>>(dst);                    // 2
    k_scan_fused<<<1, 1024>>>(batch);            // 3
    k_fill<<<gE, TB>>>(src, dst);                // 4  <- profiled launch
    k_prep_w<<<gPrep, TB>>>(Wl1, Wr1, Wl2, Wr2, Wl3, Wr3);   // 5

    // layer 1: agg(x) + x-split, GEMM -> split only
    k_agg<<<gWarpN, TB>>>(x, 0, 1);              // 6
    k_gemm_hmma<<<GEMM_BLOCKS, 256>>>(bl1, 0, 1);   // 7
    // layer 2: agg(split), GEMM -> split only
    k_agg<<<gWarpN, TB>>>(nullptr, 1, 0);        // 8
    k_gemm_hmma<<<GEMM_BLOCKS, 256>>>(bl2, 1, 1);   // 9
    // layer 3: agg(split), GEMM -> fp32 h1
    k_agg<<<gWarpN, TB>>>(nullptr, 1, 0);        // 10
    k_gemm_hmma<<<GEMM_BLOCKS, 256>>>(bl3, 2, 0);   // 11

    k_pool2<<<(NN + POOL_NODES - 1) / POOL_NODES, 128>>>(batch);  // 12
    k_head<<<BB, TB>>>(x, Wf1, bf1, Wf2, bf2, Wsm, bsm, Wnews, bnews, Wcat, bcat, out);  // 13
}